// round 8
// baseline (speedup 1.0000x reference)
#include <cuda_runtime.h>
#include <cstddef>
#include <cstdint>

#define TN_ 64
#define MN_ 64
#define ROI_ 2048
#define SPA_ 4
#define WORD_ 300
#define INF_ 2352           // ROI+SPA+WORD (weight row stride)
#define INX_ 2052           // ROI+SPA (actual GEMM K)
#define H_ 512
#define D_ 256
#define LDR_ 556            // rel_w1 row stride (D+WORD)
#define NT_ (TN_*MN_)       // 4096 tokens

// ---------------- scratch (static device globals; no allocation) ------------
__device__ float g_h1s[NT_*H_], g_h1o[NT_*H_];
__device__ float g_fsb[NT_*D_], g_fob[NT_*D_];
__device__ float g_h2s[NT_*H_], g_h2o[NT_*H_];
__device__ float g_fs[NT_*D_],  g_fo[NT_*D_];
__device__ float g_A[NT_*H_],   g_Bm[NT_*H_];
__device__ float g_sbias[H_], g_obias[H_], g_rbias[H_];
__device__ float g_weffs[H_*D_], g_weffo[H_*D_];
__device__ float g_Ms[H_*D_], g_Mo[H_*D_];
__device__ float g_W2t[D_*H_];          // rel_w2 pre-rounded to tf32

// ---------------- helpers ----------------------------------------------------

__device__ __forceinline__ unsigned f2tf(float x) {
    unsigned u;
    asm("cvt.rna.tf32.f32 %0, %1;" : "=r"(u) : "f"(x));
    return u;
}

__device__ __forceinline__ void mma_tf32(float* d, const unsigned* a, const unsigned* b) {
    asm volatile(
        "mma.sync.aligned.m16n8k8.row.col.f32.tf32.tf32.f32 "
        "{%0,%1,%2,%3}, {%4,%5,%6,%7}, {%8,%9}, {%0,%1,%2,%3};\n"
        : "+f"(d[0]), "+f"(d[1]), "+f"(d[2]), "+f"(d[3])
        : "r"(a[0]), "r"(a[1]), "r"(a[2]), "r"(a[3]),
          "r"(b[0]), "r"(b[1]));
}

__device__ __forceinline__ void cpasync16(void* dst_smem, const void* src_gmem) {
    unsigned d = (unsigned)__cvta_generic_to_shared(dst_smem);
    asm volatile("cp.async.ca.shared.global [%0], [%1], 16;\n" :: "r"(d), "l"(src_gmem));
}
__device__ __forceinline__ void cp_commit() {
    asm volatile("cp.async.commit_group;\n");
}
template <int N>
__device__ __forceinline__ void cp_wait() {
    asm volatile("cp.async.wait_group %0;\n" :: "n"(N));
}

// ---------------- small prep kernels ---------------------------------------

__global__ void prep_bias(const float* __restrict__ subj_w1, const float* __restrict__ subj_b1,
                          const float* __restrict__ obj_w1,  const float* __restrict__ obj_b1,
                          const float* __restrict__ rel_w1,  const float* __restrict__ rel_b1,
                          const float* __restrict__ subj_emb,
                          const float* __restrict__ obj_emb,
                          const float* __restrict__ pred_emb) {
    int h = blockIdx.x * blockDim.x + threadIdx.x;
    if (h >= H_) return;
    float s = subj_b1[h], o = obj_b1[h], r = rel_b1[h];
    const float* sw = subj_w1 + (size_t)h * INF_ + INX_;
    const float* ow = obj_w1  + (size_t)h * INF_ + INX_;
    const float* rw = rel_w1  + (size_t)h * LDR_ + D_;
    for (int w = 0; w < WORD_; w++) {
        s += sw[w] * subj_emb[w];
        o += ow[w] * obj_emb[w];
        r += rw[w] * pred_emb[w];
    }
    g_sbias[h] = s; g_obias[h] = o; g_rbias[h] = r;
}

__global__ void prep_weff(const float* __restrict__ fsw1,
                          const float* __restrict__ fow1) {
    int idx = blockIdx.x * blockDim.x + threadIdx.x;
    if (idx >= H_ * D_) return;
    int h = idx >> 8, k = idx & (D_ - 1);
    g_weffs[idx] = fsw1[h * (2*D_) + k] + fsw1[h * (2*D_) + D_ + k];
    g_weffo[idx] = fow1[h * (2*D_) + k] + fow1[h * (2*D_) + D_ + k];
}

__global__ void prep_w2t(const float* __restrict__ rel_w2) {
    int idx = blockIdx.x * blockDim.x + threadIdx.x;
    if (idx >= D_ * H_) return;
    g_W2t[idx] = __uint_as_float(f2tf(rel_w2[idx]));
}

// Tiled: Ms = Wd @ W_rs, Mo = Wd @ W_ro  (Wd = rel_w1[:, :D]) -> [H, D]
__global__ void __launch_bounds__(256) prep_M2(const float* __restrict__ rel_w1,
                                               const float* __restrict__ W_rs,
                                               const float* __restrict__ W_ro) {
    __shared__ float Wd[64][33];
    __shared__ float Rs[32][65];
    __shared__ float Ro[32][65];
    const int tid = threadIdx.x;
    const int k0  = blockIdx.x * 64;
    const int h0  = blockIdx.y * 64;
    const int ty  = tid >> 4;
    const int tx  = tid & 15;

    float accS[4][4], accO[4][4];
#pragma unroll
    for (int i = 0; i < 4; i++)
#pragma unroll
        for (int j = 0; j < 4; j++) { accS[i][j] = 0.f; accO[i][j] = 0.f; }

    for (int d0 = 0; d0 < D_; d0 += 32) {
        {
            const int h = tid >> 2;
            const int dc = (tid & 3) * 8;
            const float* src = rel_w1 + (size_t)(h0 + h) * LDR_ + d0 + dc;
            float4 v0 = *(const float4*)(src);
            float4 v1 = *(const float4*)(src + 4);
            Wd[h][dc+0]=v0.x; Wd[h][dc+1]=v0.y; Wd[h][dc+2]=v0.z; Wd[h][dc+3]=v0.w;
            Wd[h][dc+4]=v1.x; Wd[h][dc+5]=v1.y; Wd[h][dc+6]=v1.z; Wd[h][dc+7]=v1.w;
        }
        {
            const int d = tid >> 3;
            const int kc = (tid & 7) * 8;
            const float* ss = W_rs + (size_t)(d0 + d) * D_ + k0 + kc;
            const float* so = W_ro + (size_t)(d0 + d) * D_ + k0 + kc;
            float4 s0 = *(const float4*)(ss), s1 = *(const float4*)(ss + 4);
            float4 o0 = *(const float4*)(so), o1 = *(const float4*)(so + 4);
            Rs[d][kc+0]=s0.x; Rs[d][kc+1]=s0.y; Rs[d][kc+2]=s0.z; Rs[d][kc+3]=s0.w;
            Rs[d][kc+4]=s1.x; Rs[d][kc+5]=s1.y; Rs[d][kc+6]=s1.z; Rs[d][kc+7]=s1.w;
            Ro[d][kc+0]=o0.x; Ro[d][kc+1]=o0.y; Ro[d][kc+2]=o0.z; Ro[d][kc+3]=o0.w;
            Ro[d][kc+4]=o1.x; Ro[d][kc+5]=o1.y; Ro[d][kc+6]=o1.z; Ro[d][kc+7]=o1.w;
        }
        __syncthreads();
#pragma unroll 8
        for (int d = 0; d < 32; d++) {
            float a[4], bs[4], bo[4];
#pragma unroll
            for (int i = 0; i < 4; i++) a[i]  = Wd[ty*4+i][d];
#pragma unroll
            for (int j = 0; j < 4; j++) { bs[j] = Rs[d][tx*4+j]; bo[j] = Ro[d][tx*4+j]; }
#pragma unroll
            for (int i = 0; i < 4; i++)
#pragma unroll
                for (int j = 0; j < 4; j++) {
                    accS[i][j] += a[i] * bs[j];
                    accO[i][j] += a[i] * bo[j];
                }
        }
        __syncthreads();
    }
#pragma unroll
    for (int i = 0; i < 4; i++) {
        const int h = h0 + ty*4 + i;
        *(float4*)&g_Ms[(size_t)h * D_ + k0 + tx*4] =
            make_float4(accS[i][0], accS[i][1], accS[i][2], accS[i][3]);
        *(float4*)&g_Mo[(size_t)h * D_ + k0 + tx*4] =
            make_float4(accO[i][0], accO[i][1], accO[i][2], accO[i][3]);
    }
}

// ---------------- L1 GEMM, fused concat, dual-branch -------------------------

__global__ void __launch_bounds__(256, 2) gemm_l1(
    const float* __restrict__ roi,
    const float* __restrict__ spa,
    const float* __restrict__ w1s, const float* __restrict__ w1o,
    float* __restrict__ h1s_out, float* __restrict__ h1o_out) {
    __shared__ float As[2][128][20];
    __shared__ float Bs[2][128][20];
    const int tid  = threadIdx.x;
    const int lane = tid & 31;
    const int warp = tid >> 5;
    const int wm   = warp >> 1;
    const int wn   = warp & 1;
    const int bm   = blockIdx.y * 128;
    const int bn   = blockIdx.x * 128;
    const int br   = blockIdx.z;
    const float* Bw   = br ? w1o : w1s;
    const float* bias = br ? g_obias : g_sbias;
    float*       C    = br ? h1o_out : h1s_out;
    const int ntiles = (INX_ + 15) / 16;   // 129

    const int crow = tid >> 2;
    const int cc4  = (tid & 3) * 4;

    float acc[2][8][4];
#pragma unroll
    for (int i = 0; i < 2; i++)
#pragma unroll
        for (int j = 0; j < 8; j++)
#pragma unroll
            for (int q = 0; q < 4; q++) acc[i][j][q] = 0.f;

    auto issue = [&](int t) {
        const int s = t & 1;
        const int k = t * 16 + cc4;
#pragma unroll
        for (int it = 0; it < 2; it++) {
            const int row = crow + it * 64;
            if (k < ROI_)
                cpasync16(&As[s][row][cc4], roi + (size_t)(bm + row) * ROI_ + k);
            else if (k == ROI_)
                cpasync16(&As[s][row][cc4], spa + (size_t)(bm + row) * SPA_);
            else
                *(float4*)&As[s][row][cc4] = make_float4(0.f, 0.f, 0.f, 0.f);
            if (k <= 2048)
                cpasync16(&Bs[s][row][cc4], Bw + (size_t)(bn + row) * INF_ + k);
            else
                *(float4*)&Bs[s][row][cc4] = make_float4(0.f, 0.f, 0.f, 0.f);
        }
        cp_commit();
    };

    issue(0);
    for (int t = 0; t < ntiles; t++) {
        const int s = t & 1;
        if (t + 1 < ntiles) { issue(t + 1); cp_wait<1>(); }
        else                { cp_wait<0>(); }
        __syncthreads();
#pragma unroll
        for (int ks = 0; ks < 2; ks++) {
            const int kb = ks * 8;
            const int c  = lane & 3;
            unsigned af[2][4], bf[8][2];
#pragma unroll
            for (int mf = 0; mf < 2; mf++) {
                const int r = wm * 32 + mf * 16 + (lane >> 2);
                af[mf][0] = f2tf(As[s][r    ][kb + c]);
                af[mf][1] = f2tf(As[s][r + 8][kb + c]);
                af[mf][2] = f2tf(As[s][r    ][kb + c + 4]);
                af[mf][3] = f2tf(As[s][r + 8][kb + c + 4]);
            }
#pragma unroll
            for (int nf = 0; nf < 8; nf++) {
                const int n = wn * 64 + nf * 8 + (lane >> 2);
                bf[nf][0] = f2tf(Bs[s][n][kb + c]);
                bf[nf][1] = f2tf(Bs[s][n][kb + c + 4]);
            }
#pragma unroll
            for (int mf = 0; mf < 2; mf++)
#pragma unroll
                for (int nf = 0; nf < 8; nf++)
                    mma_tf32(acc[mf][nf], af[mf], bf[nf]);
        }
        __syncthreads();
    }

#pragma unroll
    for (int mf = 0; mf < 2; mf++) {
        const int r0 = bm + wm * 32 + mf * 16 + (lane >> 2);
#pragma unroll
        for (int nf = 0; nf < 8; nf++) {
            const int c0 = bn + wn * 64 + nf * 8 + 2 * (lane & 3);
            float x0 = fmaxf(acc[mf][nf][0] + bias[c0],     0.f);
            float x1 = fmaxf(acc[mf][nf][1] + bias[c0 + 1], 0.f);
            float x2 = fmaxf(acc[mf][nf][2] + bias[c0],     0.f);
            float x3 = fmaxf(acc[mf][nf][3] + bias[c0 + 1], 0.f);
            *(float2*)(C + (size_t)r0       * H_ + c0) = make_float2(x0, x1);
            *(float2*)(C + (size_t)(r0 + 8) * H_ + c0) = make_float2(x2, x3);
        }
    }
}

// ---------------- tf32x2 split GEMM, register-prefetch pipeline --------------
// C = act(A[M,K]@B[N,K]^T + bias).  hi/lo split ONCE at smem fill (bit-identical
// to round-7); next tile's gmem loads prefetched into registers under compute.

template <int RELU>
__global__ void __launch_bounds__(256, 2) gemm_tcx2(
    int K,
    const float* __restrict__ A0, const float* __restrict__ A1, int lda,
    const float* __restrict__ B0, const float* __restrict__ B1, int ldb,
    const float* __restrict__ bias0, const float* __restrict__ bias1,
    float* __restrict__ C0, float* __restrict__ C1, int ldc) {
    __shared__ unsigned Ash[128][20], Asl[128][20];
    __shared__ unsigned Bsh[64][20],  Bsl[64][20];
    const int tid  = threadIdx.x;
    const int lane = tid & 31;
    const int warp = tid >> 5;
    const int wm   = warp >> 1;
    const int wn   = warp & 1;
    const int bm   = blockIdx.y * 128;
    const int bn   = blockIdx.x * 64;
    const int br   = blockIdx.z;
    const float* A    = br ? A1 : A0;
    const float* B    = br ? B1 : B0;
    const float* bias = br ? bias1 : bias0;
    float*       C    = br ? C1 : C0;
    const int la   = tid >> 1;
    const int lak  = (tid & 1) * 8;
    const int lb   = tid >> 2;
    const int lbk  = (tid & 3) * 4;

    const float* arow = A + (size_t)(bm + la) * lda;
    const float* brow = B + (size_t)(bn + lb) * ldb;

    float acc[2][4][4];
#pragma unroll
    for (int i = 0; i < 2; i++)
#pragma unroll
        for (int j = 0; j < 4; j++)
#pragma unroll
            for (int q = 0; q < 4; q++) acc[i][j][q] = 0.f;

    // register prefetch of tile 0
    float4 ra0 = *(const float4*)(arow + lak);
    float4 ra1 = *(const float4*)(arow + lak + 4);
    float4 rb  = *(const float4*)(brow + lbk);

    for (int k0 = 0; k0 < K; k0 += 16) {
        // split-store the prefetched tile into smem (hi/lo computed once)
        {
            float av[8] = {ra0.x, ra0.y, ra0.z, ra0.w, ra1.x, ra1.y, ra1.z, ra1.w};
#pragma unroll
            for (int c = 0; c < 8; c++) {
                unsigned hi = f2tf(av[c]);
                Ash[la][lak + c] = hi;
                Asl[la][lak + c] = f2tf(av[c] - __uint_as_float(hi));
            }
            float bv[4] = {rb.x, rb.y, rb.z, rb.w};
#pragma unroll
            for (int c = 0; c < 4; c++) {
                unsigned hi = f2tf(bv[c]);
                Bsh[lb][lbk + c] = hi;
                Bsl[lb][lbk + c] = f2tf(bv[c] - __uint_as_float(hi));
            }
        }
        __syncthreads();
        // prefetch next tile while computing this one
        if (k0 + 16 < K) {
            ra0 = *(const float4*)(arow + k0 + 16 + lak);
            ra1 = *(const float4*)(arow + k0 + 16 + lak + 4);
            rb  = *(const float4*)(brow + k0 + 16 + lbk);
        }
#pragma unroll
        for (int ks = 0; ks < 2; ks++) {
            const int kb = ks * 8;
            unsigned afh[2][4], afl[2][4], bfh[4][2], bfl[4][2];
#pragma unroll
            for (int mf = 0; mf < 2; mf++) {
                const int r = wm * 32 + mf * 16 + (lane >> 2);
                afh[mf][0] = Ash[r    ][kb + (lane & 3)];
                afh[mf][1] = Ash[r + 8][kb + (lane & 3)];
                afh[mf][2] = Ash[r    ][kb + (lane & 3) + 4];
                afh[mf][3] = Ash[r + 8][kb + (lane & 3) + 4];
                afl[mf][0] = Asl[r    ][kb + (lane & 3)];
                afl[mf][1] = Asl[r + 8][kb + (lane & 3)];
                afl[mf][2] = Asl[r    ][kb + (lane & 3) + 4];
                afl[mf][3] = Asl[r + 8][kb + (lane & 3) + 4];
            }
#pragma unroll
            for (int nf = 0; nf < 4; nf++) {
                const int n = wn * 32 + nf * 8 + (lane >> 2);
                bfh[nf][0] = Bsh[n][kb + (lane & 3)];
                bfh[nf][1] = Bsh[n][kb + (lane & 3) + 4];
                bfl[nf][0] = Bsl[n][kb + (lane & 3)];
                bfl[nf][1] = Bsl[n][kb + (lane & 3) + 4];
            }
#pragma unroll
            for (int mf = 0; mf < 2; mf++)
#pragma unroll
                for (int nf = 0; nf < 4; nf++) {
                    mma_tf32(acc[mf][nf], afh[mf], bfl[nf]);
                    mma_tf32(acc[mf][nf], afl[mf], bfh[nf]);
                    mma_tf32(acc[mf][nf], afh[mf], bfh[nf]);
                }
        }
        __syncthreads();
    }

#pragma unroll
    for (int mf = 0; mf < 2; mf++) {
        const int r0 = bm + wm * 32 + mf * 16 + (lane >> 2);
#pragma unroll
        for (int nf = 0; nf < 4; nf++) {
            const int c0 = bn + wn * 32 + nf * 8 + 2 * (lane & 3);
            const float bv0 = bias ? bias[c0]     : 0.f;
            const float bv1 = bias ? bias[c0 + 1] : 0.f;
            float x0 = acc[mf][nf][0] + bv0, x1 = acc[mf][nf][1] + bv1;
            float x2 = acc[mf][nf][2] + bv0, x3 = acc[mf][nf][3] + bv1;
            if (RELU) { x0 = fmaxf(x0,0.f); x1 = fmaxf(x1,0.f);
                        x2 = fmaxf(x2,0.f); x3 = fmaxf(x3,0.f); }
            *(float2*)(C + (size_t)r0       * ldc + c0) = make_float2(x0, x1);
            *(float2*)(C + (size_t)(r0 + 8) * ldc + c0) = make_float2(x2, x3);
        }
    }
}

// ---------------- fused pairwise final kernel: 3-stage ring, 1 sync/tile -----
// out[P, n] = relu((A[ti]+rbias) - B[t*64+j]) @ W2t^T + rel_b2,  P = ti*64+j.
// Dynamic smem: ACs[2][512] | Bs[3][64][20] | Ws[3][128][20]  = 50176 B.

#define FT_STAGES 3
#define FT_NTILES (H_/16)       // 32
#define FT_SMEM_FLOATS (1024 + FT_STAGES*64*20 + FT_STAGES*128*20)
#define FT_SMEM_BYTES  (FT_SMEM_FLOATS * 4)

__global__ void __launch_bounds__(256, 2) final_tc3(
    const float* __restrict__ Af,   // [NT, H]
    const float* __restrict__ Bf,   // [NT, H]
    const float* __restrict__ W2t,  // [D, H] tf32-rounded
    const float* __restrict__ hb,   // g_rbias [H]
    const float* __restrict__ b2,   // rel_b2 [D]
    float* __restrict__ out) {      // [NT*64, D]
    extern __shared__ float sm[];
    float* ACs = sm;                            // [2][512]
    float* BsB = sm + 1024;                     // [3][64][20]
    float* WsB = BsB + FT_STAGES * 64 * 20;     // [3][128][20]

    const int tid  = threadIdx.x;
    const int lane = tid & 31;
    const int warp = tid >> 5;
    const int wm   = warp >> 1;
    const int wn   = warp & 1;
    const int by   = blockIdx.y;
    const int bn   = blockIdx.x * 128;
    const int ti0  = by * 2;
    const int tt   = ti0 >> 6;
    const float* bbase = Bf + (size_t)tt * 64 * H_;

    // preload ac[i][k] = Af[ti0+i][k] + rbias[k]  (published by first barrier)
    {
        const int i = tid >> 7;
        const int k = (tid & 127) * 4;
        float4 a = *(const float4*)(Af + (size_t)(ti0 + i) * H_ + k);
        float4 c = *(const float4*)(hb + k);
        *(float4*)&ACs[i * H_ + k] = make_float4(a.x + c.x, a.y + c.y, a.z + c.z, a.w + c.w);
    }

    const int crow = tid >> 2;
    const int cc4  = (tid & 3) * 4;

    float acc[2][8][4];
#pragma unroll
    for (int i = 0; i < 2; i++)
#pragma unroll
        for (int j = 0; j < 8; j++)
#pragma unroll
            for (int q = 0; q < 4; q++) acc[i][j][q] = 0.f;

    auto issue = [&](int t) {
        const int s  = t % FT_STAGES;
        const int k0 = t * 16 + cc4;
        if (crow < 64)
            cpasync16(&BsB[(s * 64 + crow) * 20 + cc4], bbase + (size_t)crow * H_ + k0);
#pragma unroll
        for (int it = 0; it < 2; it++) {
            const int row = crow + it * 64;
            cpasync16(&WsB[(s * 128 + row) * 20 + cc4], W2t + (size_t)(bn + row) * H_ + k0);
        }
        cp_commit();
    };

    issue(0);
    issue(1);
    for (int t = 0; t < FT_NTILES; t++) {
        const int s = t % FT_STAGES;
        if (t + 1 < FT_NTILES) cp_wait<1>();
        else                   cp_wait<0>();
        __syncthreads();                 // single barrier per tile
        if (t + 2 < FT_NTILES) issue(t + 2);   // lands in buffer freed by this barrier
#pragma unroll
        for (int ks = 0; ks < 2; ks++) {
            const int kb = ks * 8;
            const int c  = lane & 3;
            const int kg = t * 16 + kb + c;
            unsigned af[2][4], bf[8][2];
#pragma unroll
            for (int mf = 0; mf < 2; mf++) {
                const int r  = wm * 32 + mf * 16 + (lane >> 2);
                const int i  = r >> 6;
                const int j  = r & 63;
                const float ac0 = ACs[i * H_ + kg];
                const float ac1 = ACs[i * H_ + kg + 4];
                af[mf][0] = f2tf(fmaxf(ac0 - BsB[(s * 64 + j     ) * 20 + kb + c],     0.f));
                af[mf][1] = f2tf(fmaxf(ac0 - BsB[(s * 64 + j + 8 ) * 20 + kb + c],     0.f));
                af[mf][2] = f2tf(fmaxf(ac1 - BsB[(s * 64 + j     ) * 20 + kb + c + 4], 0.f));
                af[mf][3] = f2tf(fmaxf(ac1 - BsB[(s * 64 + j + 8 ) * 20 + kb + c + 4], 0.f));
            }
#pragma unroll
            for (int nf = 0; nf < 8; nf++) {
                const int n = wn * 64 + nf * 8 + (lane >> 2);
                bf[nf][0] = __float_as_uint(WsB[(s * 128 + n) * 20 + kb + c]);
                bf[nf][1] = __float_as_uint(WsB[(s * 128 + n) * 20 + kb + c + 4]);
            }
#pragma unroll
            for (int mf = 0; mf < 2; mf++)
#pragma unroll
                for (int nf = 0; nf < 8; nf++)
                    mma_tf32(acc[mf][nf], af[mf], bf[nf]);
        }
    }

#pragma unroll
    for (int mf = 0; mf < 2; mf++) {
        const int P0 = by * 128 + wm * 32 + mf * 16 + (lane >> 2);
#pragma unroll
        for (int nf = 0; nf < 8; nf++) {
            const int c0 = bn + wn * 64 + nf * 8 + 2 * (lane & 3);
            const float bv0 = b2[c0], bv1 = b2[c0 + 1];
            *(float2*)(out + (size_t)P0       * D_ + c0) =
                make_float2(acc[mf][nf][0] + bv0, acc[mf][nf][1] + bv1);
            *(float2*)(out + (size_t)(P0 + 8) * D_ + c0) =
                make_float2(acc[mf][nf][2] + bv0, acc[mf][nf][3] + bv1);
        }
    }
}

// ---------------- host orchestration ----------------------------------------

extern "C" void kernel_launch(void* const* d_in, const int* in_sizes, int n_in,
                              void* d_out, int out_size) {
    const float* roi      = (const float*)d_in[0];
    const float* spa      = (const float*)d_in[1];
    const float* subj_emb = (const float*)d_in[3];
    const float* obj_emb  = (const float*)d_in[4];
    const float* pred_emb = (const float*)d_in[5];
    const float* subj_w1  = (const float*)d_in[6];
    const float* subj_b1  = (const float*)d_in[7];
    const float* subj_w2  = (const float*)d_in[8];
    const float* subj_b2  = (const float*)d_in[9];
    const float* obj_w1   = (const float*)d_in[10];
    const float* obj_b1   = (const float*)d_in[11];
    const float* obj_w2   = (const float*)d_in[12];
    const float* obj_b2   = (const float*)d_in[13];
    const float* fuse_s_w1= (const float*)d_in[14];
    const float* fuse_s_b1= (const float*)d_in[15];
    const float* fuse_s_w2= (const float*)d_in[16];
    const float* fuse_s_b2= (const float*)d_in[17];
    const float* fuse_o_w1= (const float*)d_in[18];
    const float* fuse_o_b1= (const float*)d_in[19];
    const float* fuse_o_w2= (const float*)d_in[20];
    const float* fuse_o_b2= (const float*)d_in[21];
    const float* W_rs     = (const float*)d_in[22];
    const float* W_ro     = (const float*)d_in[23];
    const float* rel_w1   = (const float*)d_in[24];
    const float* rel_b1   = (const float*)d_in[25];
    const float* rel_w2   = (const float*)d_in[26];
    const float* rel_b2   = (const float*)d_in[27];
    float* out = (float*)d_out;

    float *ph1s, *ph1o, *pfsb, *pfob, *ph2s, *ph2o, *pfs, *pfo, *pA, *pB;
    float *prb, *pws, *pwo, *pMs, *pMo, *pW2t;
    cudaGetSymbolAddress((void**)&ph1s, g_h1s);
    cudaGetSymbolAddress((void**)&ph1o, g_h1o);
    cudaGetSymbolAddress((void**)&pfsb, g_fsb);
    cudaGetSymbolAddress((void**)&pfob, g_fob);
    cudaGetSymbolAddress((void**)&ph2s, g_h2s);
    cudaGetSymbolAddress((void**)&ph2o, g_h2o);
    cudaGetSymbolAddress((void**)&pfs,  g_fs);
    cudaGetSymbolAddress((void**)&pfo,  g_fo);
    cudaGetSymbolAddress((void**)&pA,   g_A);
    cudaGetSymbolAddress((void**)&pB,   g_Bm);
    cudaGetSymbolAddress((void**)&prb,  g_rbias);
    cudaGetSymbolAddress((void**)&pws,  g_weffs);
    cudaGetSymbolAddress((void**)&pwo,  g_weffo);
    cudaGetSymbolAddress((void**)&pMs,  g_Ms);
    cudaGetSymbolAddress((void**)&pMo,  g_Mo);
    cudaGetSymbolAddress((void**)&pW2t, g_W2t);

    static int attr_set = 0;
    if (!attr_set) {
        cudaFuncSetAttribute(final_tc3, cudaFuncAttributeMaxDynamicSharedMemorySize,
                             FT_SMEM_BYTES);
        attr_set = 1;
    }

    prep_bias<<<2, 256>>>(subj_w1, subj_b1, obj_w1, obj_b1, rel_w1, rel_b1,
                          subj_emb, obj_emb, pred_emb);
    prep_weff<<<(H_*D_ + 255) / 256, 256>>>(fuse_s_w1, fuse_o_w1);
    prep_M2<<<dim3(D_/64, H_/64), 256>>>(rel_w1, W_rs, W_ro);
    prep_w2t<<<(D_*H_ + 255) / 256, 256>>>(rel_w2);

    const dim3 tblk(256);
    // L1 both branches, fused concat: h1{s,o} = relu(X @ W1^T + bias)
    gemm_l1<<<dim3(H_/128, NT_/128, 2), tblk>>>(roi, spa, subj_w1, obj_w1, ph1s, ph1o);
    // L2 both branches: f{s,o}b = h1 @ W2^T + b2
    gemm_tcx2<0><<<dim3(D_/64, NT_/128, 2), tblk>>>(H_,
        ph1s, ph1o, H_, subj_w2, obj_w2, H_, subj_b2, obj_b2, pfsb, pfob, D_);
    // fuse L1 both branches: h2 = relu(fb @ weff^T + b1)
    gemm_tcx2<1><<<dim3(H_/64, NT_/128, 2), tblk>>>(D_,
        pfsb, pfob, D_, pws, pwo, D_, fuse_s_b1, fuse_o_b1, ph2s, ph2o, H_);
    // fuse L2 both branches: f{s,o} = h2 @ w2^T + b2
    gemm_tcx2<0><<<dim3(D_/64, NT_/128, 2), tblk>>>(H_,
        ph2s, ph2o, H_, fuse_s_w2, fuse_o_w2, H_, fuse_s_b2, fuse_o_b2, pfs, pfo, D_);
    // projections folded with Wd: A = fs @ Ms^T, B = fo @ Mo^T
    gemm_tcx2<0><<<dim3(H_/64, NT_/128, 2), tblk>>>(D_,
        pfs, pfo, D_, pMs, pMo, D_, nullptr, nullptr, pA, pB, H_);
    // fused pairwise ReLU-GEMM epilogue (3-stage ring) -> 256 MB output
    final_tc3<<<dim3(D_/128, NT_*64/128), tblk, FT_SMEM_BYTES>>>(
        pA, pB, pW2t, prb, rel_b2, out);
}

// round 12
// speedup vs baseline: 1.1398x; 1.1398x over previous
#include <cuda_runtime.h>
#include <cstddef>
#include <cstdint>

#define TN_ 64
#define MN_ 64
#define ROI_ 2048
#define SPA_ 4
#define WORD_ 300
#define INF_ 2352           // ROI+SPA+WORD (weight row stride)
#define INX_ 2052           // ROI+SPA (actual GEMM K)
#define H_ 512
#define D_ 256
#define LDR_ 556            // rel_w1 row stride (D+WORD)
#define NT_ (TN_*MN_)       // 4096 tokens

// ---------------- scratch (static device globals; no allocation) ------------
__device__ float g_h1s[NT_*H_], g_h1o[NT_*H_];
__device__ float g_fsb[NT_*D_], g_fob[NT_*D_];
__device__ float g_h2s[NT_*H_], g_h2o[NT_*H_];
__device__ float g_fs[NT_*D_],  g_fo[NT_*D_];
__device__ float g_A[NT_*H_],   g_Bm[NT_*H_];
__device__ float g_sbias[H_], g_obias[H_], g_rbias[H_];
__device__ float g_weffs[H_*D_], g_weffo[H_*D_];
__device__ float g_Ms[H_*D_], g_Mo[H_*D_];
__device__ float g_W2t[D_*H_];          // rel_w2 pre-rounded to tf32

// ---------------- helpers ----------------------------------------------------

__device__ __forceinline__ unsigned f2tf(float x) {
    unsigned u;
    asm("cvt.rna.tf32.f32 %0, %1;" : "=r"(u) : "f"(x));
    return u;
}

__device__ __forceinline__ void mma_tf32(float* d, const unsigned* a, const unsigned* b) {
    asm volatile(
        "mma.sync.aligned.m16n8k8.row.col.f32.tf32.tf32.f32 "
        "{%0,%1,%2,%3}, {%4,%5,%6,%7}, {%8,%9}, {%0,%1,%2,%3};\n"
        : "+f"(d[0]), "+f"(d[1]), "+f"(d[2]), "+f"(d[3])
        : "r"(a[0]), "r"(a[1]), "r"(a[2]), "r"(a[3]),
          "r"(b[0]), "r"(b[1]));
}

__device__ __forceinline__ void mma_bf16(float* d, const unsigned* a, const unsigned* b) {
    asm volatile(
        "mma.sync.aligned.m16n8k16.row.col.f32.bf16.bf16.f32 "
        "{%0,%1,%2,%3}, {%4,%5,%6,%7}, {%8,%9}, {%0,%1,%2,%3};\n"
        : "+f"(d[0]), "+f"(d[1]), "+f"(d[2]), "+f"(d[3])
        : "r"(a[0]), "r"(a[1]), "r"(a[2]), "r"(a[3]),
          "r"(b[0]), "r"(b[1]));
}

// pack (x0 -> low bf16, x1 -> high bf16); hi word + residual word
__device__ __forceinline__ void split2(float x0, float x1, unsigned& hi, unsigned& lo) {
    unsigned h;
    asm("cvt.rn.bf16x2.f32 %0, %1, %2;" : "=r"(h) : "f"(x1), "f"(x0));
    float h0 = __uint_as_float(h << 16);
    float h1 = __uint_as_float(h & 0xffff0000u);
    unsigned l;
    asm("cvt.rn.bf16x2.f32 %0, %1, %2;" : "=r"(l) : "f"(x1 - h1), "f"(x0 - h0));
    hi = h; lo = l;
}

__device__ __forceinline__ void cpasync16(void* dst_smem, const void* src_gmem) {
    unsigned d = (unsigned)__cvta_generic_to_shared(dst_smem);
    asm volatile("cp.async.ca.shared.global [%0], [%1], 16;\n" :: "r"(d), "l"(src_gmem));
}
__device__ __forceinline__ void cp_commit() {
    asm volatile("cp.async.commit_group;\n");
}
template <int N>
__device__ __forceinline__ void cp_wait() {
    asm volatile("cp.async.wait_group %0;\n" :: "n"(N));
}

// ---------------- small prep kernels ---------------------------------------

__global__ void prep_bias(const float* __restrict__ subj_w1, const float* __restrict__ subj_b1,
                          const float* __restrict__ obj_w1,  const float* __restrict__ obj_b1,
                          const float* __restrict__ rel_w1,  const float* __restrict__ rel_b1,
                          const float* __restrict__ subj_emb,
                          const float* __restrict__ obj_emb,
                          const float* __restrict__ pred_emb) {
    int h = blockIdx.x * blockDim.x + threadIdx.x;
    if (h >= H_) return;
    float s = subj_b1[h], o = obj_b1[h], r = rel_b1[h];
    const float* sw = subj_w1 + (size_t)h * INF_ + INX_;
    const float* ow = obj_w1  + (size_t)h * INF_ + INX_;
    const float* rw = rel_w1  + (size_t)h * LDR_ + D_;
    for (int w = 0; w < WORD_; w++) {
        s += sw[w] * subj_emb[w];
        o += ow[w] * obj_emb[w];
        r += rw[w] * pred_emb[w];
    }
    g_sbias[h] = s; g_obias[h] = o; g_rbias[h] = r;
}

// merged: weff (fold concat([x,x]) halves) + W2 tf32 pre-round (same index space)
__global__ void prep_wmix(const float* __restrict__ fsw1,
                          const float* __restrict__ fow1,
                          const float* __restrict__ rel_w2) {
    int idx = blockIdx.x * blockDim.x + threadIdx.x;
    if (idx >= H_ * D_) return;
    int h = idx >> 8, k = idx & (D_ - 1);
    g_weffs[idx] = fsw1[h * (2*D_) + k] + fsw1[h * (2*D_) + D_ + k];
    g_weffo[idx] = fow1[h * (2*D_) + k] + fow1[h * (2*D_) + D_ + k];
    g_W2t[idx]   = __uint_as_float(f2tf(rel_w2[idx]));
}

// Tiled: Ms = Wd @ W_rs, Mo = Wd @ W_ro  (Wd = rel_w1[:, :D]) -> [H, D]
__global__ void __launch_bounds__(256) prep_M2(const float* __restrict__ rel_w1,
                                               const float* __restrict__ W_rs,
                                               const float* __restrict__ W_ro) {
    __shared__ float Wd[64][33];
    __shared__ float Rs[32][65];
    __shared__ float Ro[32][65];
    const int tid = threadIdx.x;
    const int k0  = blockIdx.x * 64;
    const int h0  = blockIdx.y * 64;
    const int ty  = tid >> 4;
    const int tx  = tid & 15;

    float accS[4][4], accO[4][4];
#pragma unroll
    for (int i = 0; i < 4; i++)
#pragma unroll
        for (int j = 0; j < 4; j++) { accS[i][j] = 0.f; accO[i][j] = 0.f; }

    for (int d0 = 0; d0 < D_; d0 += 32) {
        {
            const int h = tid >> 2;
            const int dc = (tid & 3) * 8;
            const float* src = rel_w1 + (size_t)(h0 + h) * LDR_ + d0 + dc;
            float4 v0 = *(const float4*)(src);
            float4 v1 = *(const float4*)(src + 4);
            Wd[h][dc+0]=v0.x; Wd[h][dc+1]=v0.y; Wd[h][dc+2]=v0.z; Wd[h][dc+3]=v0.w;
            Wd[h][dc+4]=v1.x; Wd[h][dc+5]=v1.y; Wd[h][dc+6]=v1.z; Wd[h][dc+7]=v1.w;
        }
        {
            const int d = tid >> 3;
            const int kc = (tid & 7) * 8;
            const float* ss = W_rs + (size_t)(d0 + d) * D_ + k0 + kc;
            const float* so = W_ro + (size_t)(d0 + d) * D_ + k0 + kc;
            float4 s0 = *(const float4*)(ss), s1 = *(const float4*)(ss + 4);
            float4 o0 = *(const float4*)(so), o1 = *(const float4*)(so + 4);
            Rs[d][kc+0]=s0.x; Rs[d][kc+1]=s0.y; Rs[d][kc+2]=s0.z; Rs[d][kc+3]=s0.w;
            Rs[d][kc+4]=s1.x; Rs[d][kc+5]=s1.y; Rs[d][kc+6]=s1.z; Rs[d][kc+7]=s1.w;
            Ro[d][kc+0]=o0.x; Ro[d][kc+1]=o0.y; Ro[d][kc+2]=o0.z; Ro[d][kc+3]=o0.w;
            Ro[d][kc+4]=o1.x; Ro[d][kc+5]=o1.y; Ro[d][kc+6]=o1.z; Ro[d][kc+7]=o1.w;
        }
        __syncthreads();
#pragma unroll 8
        for (int d = 0; d < 32; d++) {
            float a[4], bs[4], bo[4];
#pragma unroll
            for (int i = 0; i < 4; i++) a[i]  = Wd[ty*4+i][d];
#pragma unroll
            for (int j = 0; j < 4; j++) { bs[j] = Rs[d][tx*4+j]; bo[j] = Ro[d][tx*4+j]; }
#pragma unroll
            for (int i = 0; i < 4; i++)
#pragma unroll
                for (int j = 0; j < 4; j++) {
                    accS[i][j] += a[i] * bs[j];
                    accO[i][j] += a[i] * bo[j];
                }
        }
        __syncthreads();
    }
#pragma unroll
    for (int i = 0; i < 4; i++) {
        const int h = h0 + ty*4 + i;
        *(float4*)&g_Ms[(size_t)h * D_ + k0 + tx*4] =
            make_float4(accS[i][0], accS[i][1], accS[i][2], accS[i][3]);
        *(float4*)&g_Mo[(size_t)h * D_ + k0 + tx*4] =
            make_float4(accO[i][0], accO[i][1], accO[i][2], accO[i][3]);
    }
}

// ---------------- L1 GEMM, fused concat, dual-branch (tf32) ------------------

__global__ void __launch_bounds__(256, 2) gemm_l1(
    const float* __restrict__ roi,
    const float* __restrict__ spa,
    const float* __restrict__ w1s, const float* __restrict__ w1o,
    float* __restrict__ h1s_out, float* __restrict__ h1o_out) {
    __shared__ float As[2][128][20];
    __shared__ float Bs[2][128][20];
    const int tid  = threadIdx.x;
    const int lane = tid & 31;
    const int warp = tid >> 5;
    const int wm   = warp >> 1;
    const int wn   = warp & 1;
    const int bm   = blockIdx.y * 128;
    const int bn   = blockIdx.x * 128;
    const int br   = blockIdx.z;
    const float* Bw   = br ? w1o : w1s;
    const float* bias = br ? g_obias : g_sbias;
    float*       C    = br ? h1o_out : h1s_out;
    const int ntiles = (INX_ + 15) / 16;   // 129

    const int crow = tid >> 2;
    const int cc4  = (tid & 3) * 4;

    float acc[2][8][4];
#pragma unroll
    for (int i = 0; i < 2; i++)
#pragma unroll
        for (int j = 0; j < 8; j++)
#pragma unroll
            for (int q = 0; q < 4; q++) acc[i][j][q] = 0.f;

    auto issue = [&](int t) {
        const int s = t & 1;
        const int k = t * 16 + cc4;
#pragma unroll
        for (int it = 0; it < 2; it++) {
            const int row = crow + it * 64;
            if (k < ROI_)
                cpasync16(&As[s][row][cc4], roi + (size_t)(bm + row) * ROI_ + k);
            else if (k == ROI_)
                cpasync16(&As[s][row][cc4], spa + (size_t)(bm + row) * SPA_);
            else
                *(float4*)&As[s][row][cc4] = make_float4(0.f, 0.f, 0.f, 0.f);
            if (k <= 2048)
                cpasync16(&Bs[s][row][cc4], Bw + (size_t)(bn + row) * INF_ + k);
            else
                *(float4*)&Bs[s][row][cc4] = make_float4(0.f, 0.f, 0.f, 0.f);
        }
        cp_commit();
    };

    issue(0);
    for (int t = 0; t < ntiles; t++) {
        const int s = t & 1;
        if (t + 1 < ntiles) { issue(t + 1); cp_wait<1>(); }
        else                { cp_wait<0>(); }
        __syncthreads();
#pragma unroll
        for (int ks = 0; ks < 2; ks++) {
            const int kb = ks * 8;
            const int c  = lane & 3;
            unsigned af[2][4], bf[8][2];
#pragma unroll
            for (int mf = 0; mf < 2; mf++) {
                const int r = wm * 32 + mf * 16 + (lane >> 2);
                af[mf][0] = f2tf(As[s][r    ][kb + c]);
                af[mf][1] = f2tf(As[s][r + 8][kb + c]);
                af[mf][2] = f2tf(As[s][r    ][kb + c + 4]);
                af[mf][3] = f2tf(As[s][r + 8][kb + c + 4]);
            }
#pragma unroll
            for (int nf = 0; nf < 8; nf++) {
                const int n = wn * 64 + nf * 8 + (lane >> 2);
                bf[nf][0] = f2tf(Bs[s][n][kb + c]);
                bf[nf][1] = f2tf(Bs[s][n][kb + c + 4]);
            }
#pragma unroll
            for (int mf = 0; mf < 2; mf++)
#pragma unroll
                for (int nf = 0; nf < 8; nf++)
                    mma_tf32(acc[mf][nf], af[mf], bf[nf]);
        }
        __syncthreads();
    }

#pragma unroll
    for (int mf = 0; mf < 2; mf++) {
        const int r0 = bm + wm * 32 + mf * 16 + (lane >> 2);
#pragma unroll
        for (int nf = 0; nf < 8; nf++) {
            const int c0 = bn + wn * 64 + nf * 8 + 2 * (lane & 3);
            float x0 = fmaxf(acc[mf][nf][0] + bias[c0],     0.f);
            float x1 = fmaxf(acc[mf][nf][1] + bias[c0 + 1], 0.f);
            float x2 = fmaxf(acc[mf][nf][2] + bias[c0],     0.f);
            float x3 = fmaxf(acc[mf][nf][3] + bias[c0 + 1], 0.f);
            *(float2*)(C + (size_t)r0       * H_ + c0) = make_float2(x0, x1);
            *(float2*)(C + (size_t)(r0 + 8) * H_ + c0) = make_float2(x2, x3);
        }
    }
}

// ---------------- bf16x2 split GEMM, dual-branch -----------------------------
// C = act(A[M,K]@B[N,K]^T + bias).  x = hi(bf16) + lo(bf16); products
// hi*lo + lo*hi + hi*hi on mma.m16n8k16.bf16 -> HALF the mma issue of tf32x2
// with ~2^-18 per-product error.  Tile 128x64, BK=16, register prefetch.

template <int RELU>
__global__ void __launch_bounds__(256, 2) gemm_bfx2(
    int K,
    const float* __restrict__ A0, const float* __restrict__ A1, int lda,
    const float* __restrict__ B0, const float* __restrict__ B1, int ldb,
    const float* __restrict__ bias0, const float* __restrict__ bias1,
    float* __restrict__ C0, float* __restrict__ C1, int ldc) {
    __shared__ unsigned Ash[128][12], Asl[128][12];   // 8 packed bf16x2/row + pad
    __shared__ unsigned Bsh[64][12],  Bsl[64][12];
    const int tid  = threadIdx.x;
    const int lane = tid & 31;
    const int warp = tid >> 5;
    const int wm   = warp >> 1;
    const int wn   = warp & 1;
    const int bm   = blockIdx.y * 128;
    const int bn   = blockIdx.x * 64;
    const int br   = blockIdx.z;
    const float* A    = br ? A1 : A0;
    const float* B    = br ? B1 : B0;
    const float* bias = br ? bias1 : bias0;
    float*       C    = br ? C1 : C0;
    const int la   = tid >> 1;           // A row 0..127
    const int lac  = (tid & 1) * 4;      // packed col base (4 packed = 8 floats)
    const int lakf = (tid & 1) * 8;      // float offset
    const int lb   = tid >> 2;           // B row 0..63
    const int lbc  = (tid & 3) * 2;      // packed col base (2 packed = 4 floats)
    const int lbkf = (tid & 3) * 4;      // float offset

    const float* arow = A + (size_t)(bm + la) * lda;
    const float* brow = B + (size_t)(bn + lb) * ldb;

    float acc[2][4][4];
#pragma unroll
    for (int i = 0; i < 2; i++)
#pragma unroll
        for (int j = 0; j < 4; j++)
#pragma unroll
            for (int q = 0; q < 4; q++) acc[i][j][q] = 0.f;

    float4 ra0 = *(const float4*)(arow + lakf);
    float4 ra1 = *(const float4*)(arow + lakf + 4);
    float4 rb  = *(const float4*)(brow + lbkf);

    for (int k0 = 0; k0 < K; k0 += 16) {
        {
            float av[8] = {ra0.x, ra0.y, ra0.z, ra0.w, ra1.x, ra1.y, ra1.z, ra1.w};
#pragma unroll
            for (int c = 0; c < 4; c++) {
                unsigned hi, lo;
                split2(av[2*c], av[2*c+1], hi, lo);
                Ash[la][lac + c] = hi;
                Asl[la][lac + c] = lo;
            }
            float bv[4] = {rb.x, rb.y, rb.z, rb.w};
#pragma unroll
            for (int c = 0; c < 2; c++) {
                unsigned hi, lo;
                split2(bv[2*c], bv[2*c+1], hi, lo);
                Bsh[lb][lbc + c] = hi;
                Bsl[lb][lbc + c] = lo;
            }
        }
        __syncthreads();
        if (k0 + 16 < K) {
            ra0 = *(const float4*)(arow + k0 + 16 + lakf);
            ra1 = *(const float4*)(arow + k0 + 16 + lakf + 4);
            rb  = *(const float4*)(brow + k0 + 16 + lbkf);
        }
        {
            const int c = lane & 3;
            unsigned afh[2][4], afl[2][4], bfh[4][2], bfl[4][2];
#pragma unroll
            for (int mf = 0; mf < 2; mf++) {
                const int r = wm * 32 + mf * 16 + (lane >> 2);
                afh[mf][0] = Ash[r    ][c];
                afh[mf][1] = Ash[r + 8][c];
                afh[mf][2] = Ash[r    ][c + 4];
                afh[mf][3] = Ash[r + 8][c + 4];
                afl[mf][0] = Asl[r    ][c];
                afl[mf][1] = Asl[r + 8][c];
                afl[mf][2] = Asl[r    ][c + 4];
                afl[mf][3] = Asl[r + 8][c + 4];
            }
#pragma unroll
            for (int nf = 0; nf < 4; nf++) {
                const int n = wn * 32 + nf * 8 + (lane >> 2);
                bfh[nf][0] = Bsh[n][c];
                bfh[nf][1] = Bsh[n][c + 4];
                bfl[nf][0] = Bsl[n][c];
                bfl[nf][1] = Bsl[n][c + 4];
            }
#pragma unroll
            for (int mf = 0; mf < 2; mf++)
#pragma unroll
                for (int nf = 0; nf < 4; nf++) {
                    mma_bf16(acc[mf][nf], afh[mf], bfl[nf]);
                    mma_bf16(acc[mf][nf], afl[mf], bfh[nf]);
                    mma_bf16(acc[mf][nf], afh[mf], bfh[nf]);
                }
        }
        __syncthreads();
    }

#pragma unroll
    for (int mf = 0; mf < 2; mf++) {
        const int r0 = bm + wm * 32 + mf * 16 + (lane >> 2);
#pragma unroll
        for (int nf = 0; nf < 4; nf++) {
            const int c0 = bn + wn * 32 + nf * 8 + 2 * (lane & 3);
            const float bv0 = bias ? bias[c0]     : 0.f;
            const float bv1 = bias ? bias[c0 + 1] : 0.f;
            float x0 = acc[mf][nf][0] + bv0, x1 = acc[mf][nf][1] + bv1;
            float x2 = acc[mf][nf][2] + bv0, x3 = acc[mf][nf][3] + bv1;
            if (RELU) { x0 = fmaxf(x0,0.f); x1 = fmaxf(x1,0.f);
                        x2 = fmaxf(x2,0.f); x3 = fmaxf(x3,0.f); }
            *(float2*)(C + (size_t)r0       * ldc + c0) = make_float2(x0, x1);
            *(float2*)(C + (size_t)(r0 + 8) * ldc + c0) = make_float2(x2, x3);
        }
    }
}

// ---------------- pipelined fused pairwise final kernel (round-7 body) -------
// out[P, n] = relu((A[ti]+rbias) - B[t*64+j]) @ W2t^T + rel_b2,  P = ti*64+j.

__global__ void __launch_bounds__(256, 2) final_tc2(
    const float* __restrict__ Af,   // [NT, H]
    const float* __restrict__ Bf,   // [NT, H]
    const float* __restrict__ W2t,  // [D, H] tf32-rounded
    const float* __restrict__ hb,   // g_rbias [H]
    const float* __restrict__ b2,   // rel_b2 [D]
    float* __restrict__ out) {      // [NT*64, D]
    __shared__ float ACs[2][H_];
    __shared__ float Bs[2][64][20];
    __shared__ float Ws[2][128][20];
    const int tid  = threadIdx.x;
    const int lane = tid & 31;
    const int warp = tid >> 5;
    const int wm   = warp >> 1;
    const int wn   = warp & 1;
    const int by   = blockIdx.y;
    const int bn   = blockIdx.x * 128;
    const int ti0  = by * 2;
    const int tt   = ti0 >> 6;
    const float* bbase = Bf + (size_t)tt * 64 * H_;

    {
        const int i = tid >> 7;
        const int k = (tid & 127) * 4;
        float4 a = *(const float4*)(Af + (size_t)(ti0 + i) * H_ + k);
        float4 c = *(const float4*)(hb + k);
        *(float4*)&ACs[i][k] = make_float4(a.x + c.x, a.y + c.y, a.z + c.z, a.w + c.w);
    }

    const int crow = tid >> 2;
    const int cc4  = (tid & 3) * 4;

    float acc[2][8][4];
#pragma unroll
    for (int i = 0; i < 2; i++)
#pragma unroll
        for (int j = 0; j < 8; j++)
#pragma unroll
            for (int q = 0; q < 4; q++) acc[i][j][q] = 0.f;

    auto issue = [&](int t) {
        const int s  = t & 1;
        const int k0 = t * 16 + cc4;
        if (crow < 64)
            cpasync16(&Bs[s][crow][cc4], bbase + (size_t)crow * H_ + k0);
#pragma unroll
        for (int it = 0; it < 2; it++) {
            const int row = crow + it * 64;
            cpasync16(&Ws[s][row][cc4], W2t + (size_t)(bn + row) * H_ + k0);
        }
        cp_commit();
    };

    const int NTILES = H_ / 16;   // 32
    issue(0);
    for (int t = 0; t < NTILES; t++) {
        const int s = t & 1;
        if (t + 1 < NTILES) { issue(t + 1); cp_wait<1>(); }
        else                { cp_wait<0>(); }
        __syncthreads();
#pragma unroll
        for (int ks = 0; ks < 2; ks++) {
            const int kb = ks * 8;
            const int c  = lane & 3;
            const int kg = t * 16 + kb + c;
            unsigned af[2][4], bf[8][2];
#pragma unroll
            for (int mf = 0; mf < 2; mf++) {
                const int r  = wm * 32 + mf * 16 + (lane >> 2);
                const int i  = r >> 6;
                const int j  = r & 63;
                const float ac0 = ACs[i][kg];
                const float ac1 = ACs[i][kg + 4];
                af[mf][0] = f2tf(fmaxf(ac0 - Bs[s][j    ][kb + c],     0.f));
                af[mf][1] = f2tf(fmaxf(ac0 - Bs[s][j + 8][kb + c],     0.f));
                af[mf][2] = f2tf(fmaxf(ac1 - Bs[s][j    ][kb + c + 4], 0.f));
                af[mf][3] = f2tf(fmaxf(ac1 - Bs[s][j + 8][kb + c + 4], 0.f));
            }
#pragma unroll
            for (int nf = 0; nf < 8; nf++) {
                const int n = wn * 64 + nf * 8 + (lane >> 2);
                bf[nf][0] = __float_as_uint(Ws[s][n][kb + c]);
                bf[nf][1] = __float_as_uint(Ws[s][n][kb + c + 4]);
            }
#pragma unroll
            for (int mf = 0; mf < 2; mf++)
#pragma unroll
                for (int nf = 0; nf < 8; nf++)
                    mma_tf32(acc[mf][nf], af[mf], bf[nf]);
        }
        __syncthreads();
    }

#pragma unroll
    for (int mf = 0; mf < 2; mf++) {
        const int P0 = by * 128 + wm * 32 + mf * 16 + (lane >> 2);
#pragma unroll
        for (int nf = 0; nf < 8; nf++) {
            const int c0 = bn + wn * 64 + nf * 8 + 2 * (lane & 3);
            const float bv0 = b2[c0], bv1 = b2[c0 + 1];
            *(float2*)(out + (size_t)P0       * D_ + c0) =
                make_float2(acc[mf][nf][0] + bv0, acc[mf][nf][1] + bv1);
            *(float2*)(out + (size_t)(P0 + 8) * D_ + c0) =
                make_float2(acc[mf][nf][2] + bv0, acc[mf][nf][3] + bv1);
        }
    }
}

// ---------------- host orchestration ----------------------------------------

extern "C" void kernel_launch(void* const* d_in, const int* in_sizes, int n_in,
                              void* d_out, int out_size) {
    const float* roi      = (const float*)d_in[0];
    const float* spa      = (const float*)d_in[1];
    const float* subj_emb = (const float*)d_in[3];
    const float* obj_emb  = (const float*)d_in[4];
    const float* pred_emb = (const float*)d_in[5];
    const float* subj_w1  = (const float*)d_in[6];
    const float* subj_b1  = (const float*)d_in[7];
    const float* subj_w2  = (const float*)d_in[8];
    const float* subj_b2  = (const float*)d_in[9];
    const float* obj_w1   = (const float*)d_in[10];
    const float* obj_b1   = (const float*)d_in[11];
    const float* obj_w2   = (const float*)d_in[12];
    const float* obj_b2   = (const float*)d_in[13];
    const float* fuse_s_w1= (const float*)d_in[14];
    const float* fuse_s_b1= (const float*)d_in[15];
    const float* fuse_s_w2= (const float*)d_in[16];
    const float* fuse_s_b2= (const float*)d_in[17];
    const float* fuse_o_w1= (const float*)d_in[18];
    const float* fuse_o_b1= (const float*)d_in[19];
    const float* fuse_o_w2= (const float*)d_in[20];
    const float* fuse_o_b2= (const float*)d_in[21];
    const float* W_rs     = (const float*)d_in[22];
    const float* W_ro     = (const float*)d_in[23];
    const float* rel_w1   = (const float*)d_in[24];
    const float* rel_b1   = (const float*)d_in[25];
    const float* rel_w2   = (const float*)d_in[26];
    const float* rel_b2   = (const float*)d_in[27];
    float* out = (float*)d_out;

    float *ph1s, *ph1o, *pfsb, *pfob, *ph2s, *ph2o, *pfs, *pfo, *pA, *pB;
    float *prb, *pws, *pwo, *pMs, *pMo, *pW2t;
    cudaGetSymbolAddress((void**)&ph1s, g_h1s);
    cudaGetSymbolAddress((void**)&ph1o, g_h1o);
    cudaGetSymbolAddress((void**)&pfsb, g_fsb);
    cudaGetSymbolAddress((void**)&pfob, g_fob);
    cudaGetSymbolAddress((void**)&ph2s, g_h2s);
    cudaGetSymbolAddress((void**)&ph2o, g_h2o);
    cudaGetSymbolAddress((void**)&pfs,  g_fs);
    cudaGetSymbolAddress((void**)&pfo,  g_fo);
    cudaGetSymbolAddress((void**)&pA,   g_A);
    cudaGetSymbolAddress((void**)&pB,   g_Bm);
    cudaGetSymbolAddress((void**)&prb,  g_rbias);
    cudaGetSymbolAddress((void**)&pws,  g_weffs);
    cudaGetSymbolAddress((void**)&pwo,  g_weffo);
    cudaGetSymbolAddress((void**)&pMs,  g_Ms);
    cudaGetSymbolAddress((void**)&pMo,  g_Mo);
    cudaGetSymbolAddress((void**)&pW2t, g_W2t);

    prep_bias<<<2, 256>>>(subj_w1, subj_b1, obj_w1, obj_b1, rel_w1, rel_b1,
                          subj_emb, obj_emb, pred_emb);
    prep_wmix<<<(H_*D_ + 255) / 256, 256>>>(fuse_s_w1, fuse_o_w1, rel_w2);
    prep_M2<<<dim3(D_/64, H_/64), 256>>>(rel_w1, W_rs, W_ro);

    const dim3 tblk(256);
    // L1 both branches, fused concat (tf32): h1{s,o} = relu(X @ W1^T + bias)
    gemm_l1<<<dim3(H_/128, NT_/128, 2), tblk>>>(roi, spa, subj_w1, obj_w1, ph1s, ph1o);
    // L2 both branches (bf16x2): f{s,o}b = h1 @ W2^T + b2
    gemm_bfx2<0><<<dim3(D_/64, NT_/128, 2), tblk>>>(H_,
        ph1s, ph1o, H_, subj_w2, obj_w2, H_, subj_b2, obj_b2, pfsb, pfob, D_);
    // fuse L1 both branches (bf16x2): h2 = relu(fb @ weff^T + b1)
    gemm_bfx2<1><<<dim3(H_/64, NT_/128, 2), tblk>>>(D_,
        pfsb, pfob, D_, pws, pwo, D_, fuse_s_b1, fuse_o_b1, ph2s, ph2o, H_);
    // fuse L2 both branches (bf16x2): f{s,o} = h2 @ w2^T + b2
    gemm_bfx2<0><<<dim3(D_/64, NT_/128, 2), tblk>>>(H_,
        ph2s, ph2o, H_, fuse_s_w2, fuse_o_w2, H_, fuse_s_b2, fuse_o_b2, pfs, pfo, D_);
    // projections folded with Wd (bf16x2): A = fs @ Ms^T, B = fo @ Mo^T
    gemm_bfx2<0><<<dim3(H_/64, NT_/128, 2), tblk>>>(D_,
        pfs, pfo, D_, pMs, pMo, D_, nullptr, nullptr, pA, pB, H_);
    // fused pairwise ReLU-GEMM epilogue (tf32) -> 256 MB output
    final_tc2<<<dim3(D_/128, NT_*64/128), tblk>>>(pA, pB, pW2t, prb, rel_b2, out);
}

// round 15
// speedup vs baseline: 1.1557x; 1.0140x over previous
#include <cuda_runtime.h>
#include <cstddef>
#include <cstdint>

#define TN_ 64
#define MN_ 64
#define ROI_ 2048
#define SPA_ 4
#define WORD_ 300
#define INF_ 2352           // ROI+SPA+WORD (weight row stride)
#define INX_ 2052           // ROI+SPA (actual GEMM K)
#define H_ 512
#define D_ 256
#define LDR_ 556            // rel_w1 row stride (D+WORD)
#define NT_ (TN_*MN_)       // 4096 tokens

// ---------------- scratch (static device globals; no allocation) ------------
__device__ float g_h1s[NT_*H_], g_h1o[NT_*H_];
__device__ float g_fsb[NT_*D_], g_fob[NT_*D_];
__device__ float g_h2s[NT_*H_], g_h2o[NT_*H_];
__device__ float g_fs[NT_*D_],  g_fo[NT_*D_];
__device__ float g_A[NT_*H_],   g_Bm[NT_*H_];
__device__ float g_sbias[H_], g_obias[H_], g_rbias[H_];
__device__ float g_weffs[H_*D_], g_weffo[H_*D_];
__device__ float g_Ms[H_*D_], g_Mo[H_*D_];
__device__ unsigned g_W2h[D_*H_/2];     // rel_w2 pre-packed fp16x2

// ---------------- helpers ----------------------------------------------------

__device__ __forceinline__ unsigned f2tf(float x) {
    unsigned u;
    asm("cvt.rna.tf32.f32 %0, %1;" : "=r"(u) : "f"(x));
    return u;
}

// pack (x0 -> low half, x1 -> high half) as fp16x2
__device__ __forceinline__ unsigned pack2h(float x0, float x1) {
    unsigned h;
    asm("cvt.rn.f16x2.f32 %0, %1, %2;" : "=r"(h) : "f"(x1), "f"(x0));
    return h;
}

__device__ __forceinline__ void mma_f16(float* d, const unsigned* a, const unsigned* b) {
    asm volatile(
        "mma.sync.aligned.m16n8k16.row.col.f32.f16.f16.f32 "
        "{%0,%1,%2,%3}, {%4,%5,%6,%7}, {%8,%9}, {%0,%1,%2,%3};\n"
        : "+f"(d[0]), "+f"(d[1]), "+f"(d[2]), "+f"(d[3])
        : "r"(a[0]), "r"(a[1]), "r"(a[2]), "r"(a[3]),
          "r"(b[0]), "r"(b[1]));
}

__device__ __forceinline__ void mma_bf16(float* d, const unsigned* a, const unsigned* b) {
    asm volatile(
        "mma.sync.aligned.m16n8k16.row.col.f32.bf16.bf16.f32 "
        "{%0,%1,%2,%3}, {%4,%5,%6,%7}, {%8,%9}, {%0,%1,%2,%3};\n"
        : "+f"(d[0]), "+f"(d[1]), "+f"(d[2]), "+f"(d[3])
        : "r"(a[0]), "r"(a[1]), "r"(a[2]), "r"(a[3]),
          "r"(b[0]), "r"(b[1]));
}

// bf16 hi/lo split of a float pair (hi word + residual word)
__device__ __forceinline__ void split2(float x0, float x1, unsigned& hi, unsigned& lo) {
    unsigned h;
    asm("cvt.rn.bf16x2.f32 %0, %1, %2;" : "=r"(h) : "f"(x1), "f"(x0));
    float h0 = __uint_as_float(h << 16);
    float h1 = __uint_as_float(h & 0xffff0000u);
    unsigned l;
    asm("cvt.rn.bf16x2.f32 %0, %1, %2;" : "=r"(l) : "f"(x1 - h1), "f"(x0 - h0));
    hi = h; lo = l;
}

__device__ __forceinline__ void cpasync16(void* dst_smem, const void* src_gmem) {
    unsigned d = (unsigned)__cvta_generic_to_shared(dst_smem);
    asm volatile("cp.async.ca.shared.global [%0], [%1], 16;\n" :: "r"(d), "l"(src_gmem));
}
__device__ __forceinline__ void cp_commit() {
    asm volatile("cp.async.commit_group;\n");
}
template <int N>
__device__ __forceinline__ void cp_wait() {
    asm volatile("cp.async.wait_group %0;\n" :: "n"(N));
}

// ---------------- small prep kernels ---------------------------------------

__global__ void prep_bias(const float* __restrict__ subj_w1, const float* __restrict__ subj_b1,
                          const float* __restrict__ obj_w1,  const float* __restrict__ obj_b1,
                          const float* __restrict__ rel_w1,  const float* __restrict__ rel_b1,
                          const float* __restrict__ subj_emb,
                          const float* __restrict__ obj_emb,
                          const float* __restrict__ pred_emb) {
    int h = blockIdx.x * blockDim.x + threadIdx.x;
    if (h >= H_) return;
    float s = subj_b1[h], o = obj_b1[h], r = rel_b1[h];
    const float* sw = subj_w1 + (size_t)h * INF_ + INX_;
    const float* ow = obj_w1  + (size_t)h * INF_ + INX_;
    const float* rw = rel_w1  + (size_t)h * LDR_ + D_;
    for (int w = 0; w < WORD_; w++) {
        s += sw[w] * subj_emb[w];
        o += ow[w] * obj_emb[w];
        r += rw[w] * pred_emb[w];
    }
    g_sbias[h] = s; g_obias[h] = o; g_rbias[h] = r;
}

// merged: weff (fold concat([x,x]) halves) + W2 fp16x2 pre-pack
__global__ void prep_wmix(const float* __restrict__ fsw1,
                          const float* __restrict__ fow1,
                          const float* __restrict__ rel_w2) {
    int idx = blockIdx.x * blockDim.x + threadIdx.x;
    if (idx >= H_ * D_) return;
    int h = idx >> 8, k = idx & (D_ - 1);
    g_weffs[idx] = fsw1[h * (2*D_) + k] + fsw1[h * (2*D_) + D_ + k];
    g_weffo[idx] = fow1[h * (2*D_) + k] + fow1[h * (2*D_) + D_ + k];
    if (idx < H_ * D_ / 2)
        g_W2h[idx] = pack2h(rel_w2[2*idx], rel_w2[2*idx+1]);
}

// Tiled: Ms = Wd @ W_rs, Mo = Wd @ W_ro  (Wd = rel_w1[:, :D]) -> [H, D]
__global__ void __launch_bounds__(256) prep_M2(const float* __restrict__ rel_w1,
                                               const float* __restrict__ W_rs,
                                               const float* __restrict__ W_ro) {
    __shared__ float Wd[64][33];
    __shared__ float Rs[32][65];
    __shared__ float Ro[32][65];
    const int tid = threadIdx.x;
    const int k0  = blockIdx.x * 64;
    const int h0  = blockIdx.y * 64;
    const int ty  = tid >> 4;
    const int tx  = tid & 15;

    float accS[4][4], accO[4][4];
#pragma unroll
    for (int i = 0; i < 4; i++)
#pragma unroll
        for (int j = 0; j < 4; j++) { accS[i][j] = 0.f; accO[i][j] = 0.f; }

    for (int d0 = 0; d0 < D_; d0 += 32) {
        {
            const int h = tid >> 2;
            const int dc = (tid & 3) * 8;
            const float* src = rel_w1 + (size_t)(h0 + h) * LDR_ + d0 + dc;
            float4 v0 = *(const float4*)(src);
            float4 v1 = *(const float4*)(src + 4);
            Wd[h][dc+0]=v0.x; Wd[h][dc+1]=v0.y; Wd[h][dc+2]=v0.z; Wd[h][dc+3]=v0.w;
            Wd[h][dc+4]=v1.x; Wd[h][dc+5]=v1.y; Wd[h][dc+6]=v1.z; Wd[h][dc+7]=v1.w;
        }
        {
            const int d = tid >> 3;
            const int kc = (tid & 7) * 8;
            const float* ss = W_rs + (size_t)(d0 + d) * D_ + k0 + kc;
            const float* so = W_ro + (size_t)(d0 + d) * D_ + k0 + kc;
            float4 s0 = *(const float4*)(ss), s1 = *(const float4*)(ss + 4);
            float4 o0 = *(const float4*)(so), o1 = *(const float4*)(so + 4);
            Rs[d][kc+0]=s0.x; Rs[d][kc+1]=s0.y; Rs[d][kc+2]=s0.z; Rs[d][kc+3]=s0.w;
            Rs[d][kc+4]=s1.x; Rs[d][kc+5]=s1.y; Rs[d][kc+6]=s1.z; Rs[d][kc+7]=s1.w;
            Ro[d][kc+0]=o0.x; Ro[d][kc+1]=o0.y; Ro[d][kc+2]=o0.z; Ro[d][kc+3]=o0.w;
            Ro[d][kc+4]=o1.x; Ro[d][kc+5]=o1.y; Ro[d][kc+6]=o1.z; Ro[d][kc+7]=o1.w;
        }
        __syncthreads();
#pragma unroll 8
        for (int d = 0; d < 32; d++) {
            float a[4], bs[4], bo[4];
#pragma unroll
            for (int i = 0; i < 4; i++) a[i]  = Wd[ty*4+i][d];
#pragma unroll
            for (int j = 0; j < 4; j++) { bs[j] = Rs[d][tx*4+j]; bo[j] = Ro[d][tx*4+j]; }
#pragma unroll
            for (int i = 0; i < 4; i++)
#pragma unroll
                for (int j = 0; j < 4; j++) {
                    accS[i][j] += a[i] * bs[j];
                    accO[i][j] += a[i] * bo[j];
                }
        }
        __syncthreads();
    }
#pragma unroll
    for (int i = 0; i < 4; i++) {
        const int h = h0 + ty*4 + i;
        *(float4*)&g_Ms[(size_t)h * D_ + k0 + tx*4] =
            make_float4(accS[i][0], accS[i][1], accS[i][2], accS[i][3]);
        *(float4*)&g_Mo[(size_t)h * D_ + k0 + tx*4] =
            make_float4(accO[i][0], accO[i][1], accO[i][2], accO[i][3]);
    }
}

// ---------------- L1 GEMM, fused concat, dual-branch (fp16) ------------------
// h1 = relu([roi|spa] @ W1[:, :2052]^T + bias).  fp16 fragments (same 10-bit
// mantissa as tf32, HALF the mma issue).  Block tile 128x128, BK=16, 2-stage.

__global__ void __launch_bounds__(256, 2) gemm_l1(
    const float* __restrict__ roi,
    const float* __restrict__ spa,
    const float* __restrict__ w1s, const float* __restrict__ w1o,
    float* __restrict__ h1s_out, float* __restrict__ h1o_out) {
    __shared__ float As[2][128][20];
    __shared__ float Bs[2][128][20];
    const int tid  = threadIdx.x;
    const int lane = tid & 31;
    const int warp = tid >> 5;
    const int wm   = warp >> 1;
    const int wn   = warp & 1;
    const int bm   = blockIdx.y * 128;
    const int bn   = blockIdx.x * 128;
    const int br   = blockIdx.z;
    const float* Bw   = br ? w1o : w1s;
    const float* bias = br ? g_obias : g_sbias;
    float*       C    = br ? h1o_out : h1s_out;
    const int ntiles = (INX_ + 15) / 16;   // 129

    const int crow = tid >> 2;
    const int cc4  = (tid & 3) * 4;

    float acc[2][8][4];
#pragma unroll
    for (int i = 0; i < 2; i++)
#pragma unroll
        for (int j = 0; j < 8; j++)
#pragma unroll
            for (int q = 0; q < 4; q++) acc[i][j][q] = 0.f;

    auto issue = [&](int t) {
        const int s = t & 1;
        const int k = t * 16 + cc4;
#pragma unroll
        for (int it = 0; it < 2; it++) {
            const int row = crow + it * 64;
            if (k < ROI_)
                cpasync16(&As[s][row][cc4], roi + (size_t)(bm + row) * ROI_ + k);
            else if (k == ROI_)
                cpasync16(&As[s][row][cc4], spa + (size_t)(bm + row) * SPA_);
            else
                *(float4*)&As[s][row][cc4] = make_float4(0.f, 0.f, 0.f, 0.f);
            if (k <= 2048)
                cpasync16(&Bs[s][row][cc4], Bw + (size_t)(bn + row) * INF_ + k);
            else
                *(float4*)&Bs[s][row][cc4] = make_float4(0.f, 0.f, 0.f, 0.f);
        }
        cp_commit();
    };

    issue(0);
    for (int t = 0; t < ntiles; t++) {
        const int s = t & 1;
        if (t + 1 < ntiles) { issue(t + 1); cp_wait<1>(); }
        else                { cp_wait<0>(); }
        __syncthreads();
        {
            const int c  = lane & 3;
            const int kl = 2 * c;          // low k-pair offset
            const int kh = 8 + 2 * c;      // high k-pair offset
            unsigned af[2][4], bf[8][2];
#pragma unroll
            for (int mf = 0; mf < 2; mf++) {
                const int r = wm * 32 + mf * 16 + (lane >> 2);
                af[mf][0] = pack2h(As[s][r    ][kl], As[s][r    ][kl + 1]);
                af[mf][1] = pack2h(As[s][r + 8][kl], As[s][r + 8][kl + 1]);
                af[mf][2] = pack2h(As[s][r    ][kh], As[s][r    ][kh + 1]);
                af[mf][3] = pack2h(As[s][r + 8][kh], As[s][r + 8][kh + 1]);
            }
#pragma unroll
            for (int nf = 0; nf < 8; nf++) {
                const int n = wn * 64 + nf * 8 + (lane >> 2);
                bf[nf][0] = pack2h(Bs[s][n][kl], Bs[s][n][kl + 1]);
                bf[nf][1] = pack2h(Bs[s][n][kh], Bs[s][n][kh + 1]);
            }
#pragma unroll
            for (int mf = 0; mf < 2; mf++)
#pragma unroll
                for (int nf = 0; nf < 8; nf++)
                    mma_f16(acc[mf][nf], af[mf], bf[nf]);
        }
        __syncthreads();
    }

#pragma unroll
    for (int mf = 0; mf < 2; mf++) {
        const int r0 = bm + wm * 32 + mf * 16 + (lane >> 2);
#pragma unroll
        for (int nf = 0; nf < 8; nf++) {
            const int c0 = bn + wn * 64 + nf * 8 + 2 * (lane & 3);
            float x0 = fmaxf(acc[mf][nf][0] + bias[c0],     0.f);
            float x1 = fmaxf(acc[mf][nf][1] + bias[c0 + 1], 0.f);
            float x2 = fmaxf(acc[mf][nf][2] + bias[c0],     0.f);
            float x3 = fmaxf(acc[mf][nf][3] + bias[c0 + 1], 0.f);
            *(float2*)(C + (size_t)r0       * H_ + c0) = make_float2(x0, x1);
            *(float2*)(C + (size_t)(r0 + 8) * H_ + c0) = make_float2(x2, x3);
        }
    }
}

// ---------------- bf16x2 split GEMM, dual-branch (unchanged) -----------------

template <int RELU>
__global__ void __launch_bounds__(256, 2) gemm_bfx2(
    int K,
    const float* __restrict__ A0, const float* __restrict__ A1, int lda,
    const float* __restrict__ B0, const float* __restrict__ B1, int ldb,
    const float* __restrict__ bias0, const float* __restrict__ bias1,
    float* __restrict__ C0, float* __restrict__ C1, int ldc) {
    __shared__ unsigned Ash[128][12], Asl[128][12];
    __shared__ unsigned Bsh[64][12],  Bsl[64][12];
    const int tid  = threadIdx.x;
    const int lane = tid & 31;
    const int warp = tid >> 5;
    const int wm   = warp >> 1;
    const int wn   = warp & 1;
    const int bm   = blockIdx.y * 128;
    const int bn   = blockIdx.x * 64;
    const int br   = blockIdx.z;
    const float* A    = br ? A1 : A0;
    const float* B    = br ? B1 : B0;
    const float* bias = br ? bias1 : bias0;
    float*       C    = br ? C1 : C0;
    const int la   = tid >> 1;
    const int lac  = (tid & 1) * 4;
    const int lakf = (tid & 1) * 8;
    const int lb   = tid >> 2;
    const int lbc  = (tid & 3) * 2;
    const int lbkf = (tid & 3) * 4;

    const float* arow = A + (size_t)(bm + la) * lda;
    const float* brow = B + (size_t)(bn + lb) * ldb;

    float acc[2][4][4];
#pragma unroll
    for (int i = 0; i < 2; i++)
#pragma unroll
        for (int j = 0; j < 4; j++)
#pragma unroll
            for (int q = 0; q < 4; q++) acc[i][j][q] = 0.f;

    float4 ra0 = *(const float4*)(arow + lakf);
    float4 ra1 = *(const float4*)(arow + lakf + 4);
    float4 rb  = *(const float4*)(brow + lbkf);

    for (int k0 = 0; k0 < K; k0 += 16) {
        {
            float av[8] = {ra0.x, ra0.y, ra0.z, ra0.w, ra1.x, ra1.y, ra1.z, ra1.w};
#pragma unroll
            for (int c = 0; c < 4; c++) {
                unsigned hi, lo;
                split2(av[2*c], av[2*c+1], hi, lo);
                Ash[la][lac + c] = hi;
                Asl[la][lac + c] = lo;
            }
            float bv[4] = {rb.x, rb.y, rb.z, rb.w};
#pragma unroll
            for (int c = 0; c < 2; c++) {
                unsigned hi, lo;
                split2(bv[2*c], bv[2*c+1], hi, lo);
                Bsh[lb][lbc + c] = hi;
                Bsl[lb][lbc + c] = lo;
            }
        }
        __syncthreads();
        if (k0 + 16 < K) {
            ra0 = *(const float4*)(arow + k0 + 16 + lakf);
            ra1 = *(const float4*)(arow + k0 + 16 + lakf + 4);
            rb  = *(const float4*)(brow + k0 + 16 + lbkf);
        }
        {
            const int c = lane & 3;
            unsigned afh[2][4], afl[2][4], bfh[4][2], bfl[4][2];
#pragma unroll
            for (int mf = 0; mf < 2; mf++) {
                const int r = wm * 32 + mf * 16 + (lane >> 2);
                afh[mf][0] = Ash[r    ][c];
                afh[mf][1] = Ash[r + 8][c];
                afh[mf][2] = Ash[r    ][c + 4];
                afh[mf][3] = Ash[r + 8][c + 4];
                afl[mf][0] = Asl[r    ][c];
                afl[mf][1] = Asl[r + 8][c];
                afl[mf][2] = Asl[r    ][c + 4];
                afl[mf][3] = Asl[r + 8][c + 4];
            }
#pragma unroll
            for (int nf = 0; nf < 4; nf++) {
                const int n = wn * 32 + nf * 8 + (lane >> 2);
                bfh[nf][0] = Bsh[n][c];
                bfh[nf][1] = Bsh[n][c + 4];
                bfl[nf][0] = Bsl[n][c];
                bfl[nf][1] = Bsl[n][c + 4];
            }
#pragma unroll
            for (int mf = 0; mf < 2; mf++)
#pragma unroll
                for (int nf = 0; nf < 4; nf++) {
                    mma_bf16(acc[mf][nf], afh[mf], bfl[nf]);
                    mma_bf16(acc[mf][nf], afl[mf], bfh[nf]);
                    mma_bf16(acc[mf][nf], afh[mf], bfh[nf]);
                }
        }
        __syncthreads();
    }

#pragma unroll
    for (int mf = 0; mf < 2; mf++) {
        const int r0 = bm + wm * 32 + mf * 16 + (lane >> 2);
#pragma unroll
        for (int nf = 0; nf < 4; nf++) {
            const int c0 = bn + wn * 32 + nf * 8 + 2 * (lane & 3);
            const float bv0 = bias ? bias[c0]     : 0.f;
            const float bv1 = bias ? bias[c0 + 1] : 0.f;
            float x0 = acc[mf][nf][0] + bv0, x1 = acc[mf][nf][1] + bv1;
            float x2 = acc[mf][nf][2] + bv0, x3 = acc[mf][nf][3] + bv1;
            if (RELU) { x0 = fmaxf(x0,0.f); x1 = fmaxf(x1,0.f);
                        x2 = fmaxf(x2,0.f); x3 = fmaxf(x3,0.f); }
            *(float2*)(C + (size_t)r0       * ldc + c0) = make_float2(x0, x1);
            *(float2*)(C + (size_t)(r0 + 8) * ldc + c0) = make_float2(x2, x3);
        }
    }
}

// ---------------- fused pairwise final kernel (fp16) -------------------------
// out[P, n] = relu((A[ti]+rbias) - B[t*64+j]) @ W2^T + rel_b2,  P = ti*64+j.
// fp16 fragments (same mantissa as tf32, half the mma issue); W2 pre-packed.

__global__ void __launch_bounds__(256, 2) final_f16(
    const float* __restrict__ Af,      // [NT, H]
    const float* __restrict__ Bf,      // [NT, H]
    const unsigned* __restrict__ W2h,  // [D, H/2] fp16x2-packed
    const float* __restrict__ hb,      // g_rbias [H]
    const float* __restrict__ b2,      // rel_b2 [D]
    float* __restrict__ out) {         // [NT*64, D]
    __shared__ float    ACs[2][H_];
    __shared__ float    Bs[2][64][20];
    __shared__ unsigned Wh[2][128][12];
    const int tid  = threadIdx.x;
    const int lane = tid & 31;
    const int warp = tid >> 5;
    const int wm   = warp >> 1;
    const int wn   = warp & 1;
    const int by   = blockIdx.y;
    const int bn   = blockIdx.x * 128;
    const int ti0  = by * 2;
    const int tt   = ti0 >> 6;
    const float* bbase = Bf + (size_t)tt * 64 * H_;

    {
        const int i = tid >> 7;
        const int k = (tid & 127) * 4;
        float4 a = *(const float4*)(Af + (size_t)(ti0 + i) * H_ + k);
        float4 c = *(const float4*)(hb + k);
        *(float4*)&ACs[i][k] = make_float4(a.x + c.x, a.y + c.y, a.z + c.z, a.w + c.w);
    }

    const int crow = tid >> 2;          // Bs: 64 rows x 4 chunks
    const int cc4  = (tid & 3) * 4;
    const int wrow = tid >> 1;          // Wh: 128 rows x 2 chunks
    const int wc4  = (tid & 1) * 4;     // packed-uint offset

    float acc[2][8][4];
#pragma unroll
    for (int i = 0; i < 2; i++)
#pragma unroll
        for (int j = 0; j < 8; j++)
#pragma unroll
            for (int q = 0; q < 4; q++) acc[i][j][q] = 0.f;

    auto issue = [&](int t) {
        const int s = t & 1;
        cpasync16(&Bs[s][crow][cc4], bbase + (size_t)crow * H_ + t * 16 + cc4);
        cpasync16(&Wh[s][wrow][wc4], W2h + (size_t)(bn + wrow) * (H_/2) + t * 8 + wc4);
        cp_commit();
    };

    const int NTILES = H_ / 16;   // 32
    issue(0);
    for (int t = 0; t < NTILES; t++) {
        const int s = t & 1;
        if (t + 1 < NTILES) { issue(t + 1); cp_wait<1>(); }
        else                { cp_wait<0>(); }
        __syncthreads();
        {
            const int c  = lane & 3;
            const int kl = 2 * c;            // low k-pair (local)
            const int kh = 8 + 2 * c;        // high k-pair (local)
            const int kg = t * 16;
            unsigned af[2][4], bf[8][2];
#pragma unroll
            for (int mf = 0; mf < 2; mf++) {
                const int r  = wm * 32 + mf * 16 + (lane >> 2);
                const int i  = r >> 6;
                const int j  = r & 63;
                const float a00 = ACs[i][kg + kl],     a01 = ACs[i][kg + kl + 1];
                const float a10 = ACs[i][kg + kh],     a11 = ACs[i][kg + kh + 1];
                af[mf][0] = pack2h(fmaxf(a00 - Bs[s][j    ][kl], 0.f),
                                   fmaxf(a01 - Bs[s][j    ][kl + 1], 0.f));
                af[mf][1] = pack2h(fmaxf(a00 - Bs[s][j + 8][kl], 0.f),
                                   fmaxf(a01 - Bs[s][j + 8][kl + 1], 0.f));
                af[mf][2] = pack2h(fmaxf(a10 - Bs[s][j    ][kh], 0.f),
                                   fmaxf(a11 - Bs[s][j    ][kh + 1], 0.f));
                af[mf][3] = pack2h(fmaxf(a10 - Bs[s][j + 8][kh], 0.f),
                                   fmaxf(a11 - Bs[s][j + 8][kh + 1], 0.f));
            }
#pragma unroll
            for (int nf = 0; nf < 8; nf++) {
                const int n = wn * 64 + nf * 8 + (lane >> 2);
                bf[nf][0] = Wh[s][n][c];
                bf[nf][1] = Wh[s][n][c + 4];
            }
#pragma unroll
            for (int mf = 0; mf < 2; mf++)
#pragma unroll
                for (int nf = 0; nf < 8; nf++)
                    mma_f16(acc[mf][nf], af[mf], bf[nf]);
        }
        __syncthreads();
    }

#pragma unroll
    for (int mf = 0; mf < 2; mf++) {
        const int P0 = by * 128 + wm * 32 + mf * 16 + (lane >> 2);
#pragma unroll
        for (int nf = 0; nf < 8; nf++) {
            const int c0 = bn + wn * 64 + nf * 8 + 2 * (lane & 3);
            const float bv0 = b2[c0], bv1 = b2[c0 + 1];
            *(float2*)(out + (size_t)P0       * D_ + c0) =
                make_float2(acc[mf][nf][0] + bv0, acc[mf][nf][1] + bv1);
            *(float2*)(out + (size_t)(P0 + 8) * D_ + c0) =
                make_float2(acc[mf][nf][2] + bv0, acc[mf][nf][3] + bv1);
        }
    }
}

// ---------------- host orchestration ----------------------------------------

extern "C" void kernel_launch(void* const* d_in, const int* in_sizes, int n_in,
                              void* d_out, int out_size) {
    const float* roi      = (const float*)d_in[0];
    const float* spa      = (const float*)d_in[1];
    const float* subj_emb = (const float*)d_in[3];
    const float* obj_emb  = (const float*)d_in[4];
    const float* pred_emb = (const float*)d_in[5];
    const float* subj_w1  = (const float*)d_in[6];
    const float* subj_b1  = (const float*)d_in[7];
    const float* subj_w2  = (const float*)d_in[8];
    const float* subj_b2  = (const float*)d_in[9];
    const float* obj_w1   = (const float*)d_in[10];
    const float* obj_b1   = (const float*)d_in[11];
    const float* obj_w2   = (const float*)d_in[12];
    const float* obj_b2   = (const float*)d_in[13];
    const float* fuse_s_w1= (const float*)d_in[14];
    const float* fuse_s_b1= (const float*)d_in[15];
    const float* fuse_s_w2= (const float*)d_in[16];
    const float* fuse_s_b2= (const float*)d_in[17];
    const float* fuse_o_w1= (const float*)d_in[18];
    const float* fuse_o_b1= (const float*)d_in[19];
    const float* fuse_o_w2= (const float*)d_in[20];
    const float* fuse_o_b2= (const float*)d_in[21];
    const float* W_rs     = (const float*)d_in[22];
    const float* W_ro     = (const float*)d_in[23];
    const float* rel_w1   = (const float*)d_in[24];
    const float* rel_b1   = (const float*)d_in[25];
    const float* rel_w2   = (const float*)d_in[26];
    const float* rel_b2   = (const float*)d_in[27];
    float* out = (float*)d_out;

    float *ph1s, *ph1o, *pfsb, *pfob, *ph2s, *ph2o, *pfs, *pfo, *pA, *pB;
    float *prb, *pws, *pwo, *pMs, *pMo;
    unsigned *pW2h;
    cudaGetSymbolAddress((void**)&ph1s, g_h1s);
    cudaGetSymbolAddress((void**)&ph1o, g_h1o);
    cudaGetSymbolAddress((void**)&pfsb, g_fsb);
    cudaGetSymbolAddress((void**)&pfob, g_fob);
    cudaGetSymbolAddress((void**)&ph2s, g_h2s);
    cudaGetSymbolAddress((void**)&ph2o, g_h2o);
    cudaGetSymbolAddress((void**)&pfs,  g_fs);
    cudaGetSymbolAddress((void**)&pfo,  g_fo);
    cudaGetSymbolAddress((void**)&pA,   g_A);
    cudaGetSymbolAddress((void**)&pB,   g_Bm);
    cudaGetSymbolAddress((void**)&prb,  g_rbias);
    cudaGetSymbolAddress((void**)&pws,  g_weffs);
    cudaGetSymbolAddress((void**)&pwo,  g_weffo);
    cudaGetSymbolAddress((void**)&pMs,  g_Ms);
    cudaGetSymbolAddress((void**)&pMo,  g_Mo);
    cudaGetSymbolAddress((void**)&pW2h, g_W2h);

    prep_bias<<<2, 256>>>(subj_w1, subj_b1, obj_w1, obj_b1, rel_w1, rel_b1,
                          subj_emb, obj_emb, pred_emb);
    prep_wmix<<<(H_*D_ + 255) / 256, 256>>>(fuse_s_w1, fuse_o_w1, rel_w2);
    prep_M2<<<dim3(D_/64, H_/64), 256>>>(rel_w1, W_rs, W_ro);

    const dim3 tblk(256);
    // L1 both branches, fused concat (fp16): h1{s,o} = relu(X @ W1^T + bias)
    gemm_l1<<<dim3(H_/128, NT_/128, 2), tblk>>>(roi, spa, subj_w1, obj_w1, ph1s, ph1o);
    // L2 both branches (bf16x2): f{s,o}b = h1 @ W2^T + b2
    gemm_bfx2<0><<<dim3(D_/64, NT_/128, 2), tblk>>>(H_,
        ph1s, ph1o, H_, subj_w2, obj_w2, H_, subj_b2, obj_b2, pfsb, pfob, D_);
    // fuse L1 both branches (bf16x2): h2 = relu(fb @ weff^T + b1)
    gemm_bfx2<1><<<dim3(H_/64, NT_/128, 2), tblk>>>(D_,
        pfsb, pfob, D_, pws, pwo, D_, fuse_s_b1, fuse_o_b1, ph2s, ph2o, H_);
    // fuse L2 both branches (bf16x2): f{s,o} = h2 @ w2^T + b2
    gemm_bfx2<0><<<dim3(D_/64, NT_/128, 2), tblk>>>(H_,
        ph2s, ph2o, H_, fuse_s_w2, fuse_o_w2, H_, fuse_s_b2, fuse_o_b2, pfs, pfo, D_);
    // projections folded with Wd (bf16x2): A = fs @ Ms^T, B = fo @ Mo^T
    gemm_bfx2<0><<<dim3(H_/64, NT_/128, 2), tblk>>>(D_,
        pfs, pfo, D_, pMs, pMo, D_, nullptr, nullptr, pA, pB, H_);
    // fused pairwise ReLU-GEMM epilogue (fp16) -> 256 MB output
    final_f16<<<dim3(D_/128, NT_*64/128), tblk>>>(pA, pB, pW2h, prb, rel_b2, out);
}